// round 15
// baseline (speedup 1.0000x reference)
#include <cuda_runtime.h>
#include <cuda_fp16.h>

// CapsuleLayer dynamic routing, GB300 sm_103a.
// B=32, IN_CAPS=1152, P=64, NUM_CAPS=32, Q=64, NUM_ROUTING=3.
//
// hat[b,i,c,q] = sum_p x[b,i,p] * W[i,c,p,q]   (tf32 mma.sync, stored fp16)
// r0: c0 = softmax_c(bias) batch-independent -> S0 partials inside GEMM (fp32)
// r1: b1 = bias + <hat,v0>_q ; S1 = sum_i softmax_c(b1)*hat ; v1=squash(S1)
// r2: b2 = bias + <hat,v0+v1>_q ; S2 = ... ; out = squash(S2)
// All S sums via non-atomic per-block partials, reduced in parallel squash kernels.

#define BB 32
#define IC 1152
#define PP 64
#define NC 32
#define QQ 64
#define HAT_ELEMS (BB * IC * NC * QQ)
#define SV (BB * NC * QQ)
#define NIBLK 36     // gemm i-blocks
#define NRBLK 64     // route i-blocks (IC / RICH)

// ---------------- device scratch ----------------
__device__ __align__(16) __half g_hat[HAT_ELEMS];      // 151 MB
__device__ __align__(16) float g_S0p[NIBLK * SV];      // 9.4 MB partials
__device__ __align__(16) float g_S1p[NRBLK * SV];      // 16.8 MB partials
__device__ __align__(16) float g_S2p[NRBLK * SV];      // 16.8 MB partials
__device__ __align__(16) float g_v0[SV];
__device__ __align__(16) float g_v01[SV];

// ---------------- helpers ----------------
__device__ __forceinline__ unsigned int fu(float f) { return __float_as_uint(f); }

__device__ __forceinline__ void cp16(const void* smem_dst, const void* gmem_src) {
    unsigned int s = (unsigned int)__cvta_generic_to_shared(smem_dst);
    asm volatile("cp.async.cg.shared.global [%0], [%1], 16;" :: "r"(s), "l"(gmem_src));
}
__device__ __forceinline__ void cp_commit() {
    asm volatile("cp.async.commit_group;");
}
template <int N>
__device__ __forceinline__ void cp_wait() {
    asm volatile("cp.async.wait_group %0;" :: "n"(N));
}

// tf32 m16n8k8: D += A*B. A row-major [16x8], B col-major [8x8], fp32 accum.
#define MMA_TF32(D, A, B0, B1)                                            \
    asm volatile(                                                          \
        "mma.sync.aligned.m16n8k8.row.col.f32.tf32.tf32.f32 "              \
        "{%0,%1,%2,%3},{%4,%5,%6,%7},{%8,%9},{%0,%1,%2,%3};"               \
        : "+f"((D)[0]), "+f"((D)[1]), "+f"((D)[2]), "+f"((D)[3])           \
        : "r"(fu((A)[0])), "r"(fu((A)[1])), "r"(fu((A)[2])), "r"(fu((A)[3])), \
          "r"(fu(B0)), "r"(fu(B1)))

// ---------------- GEMM (tf32): hat (fp16, staged) + S0 partials + fused c0 --
// Grid (16 cpairs, 36 iblocks), 128 threads (4 warps), 2 CTAs/SM.
#define ICH 32
#define WS_STRIDE 136     // 136 % 32 == 8 -> bank = 8k+n : conflict-free B reads
#define XS_STRIDE 68      // 68 % 32 == 4  -> bank = 4b+p : conflict-free A reads
#define HS_STRIDE 136     // halfs per staging row
#define WS_FLOATS (PP * WS_STRIDE)   // 8704
#define XS_FLOATS (BB * XS_STRIDE)   // 2176
#define HS_FLOATS (BB * HS_STRIDE / 2)
#define GEMM_SMEM_BYTES ((2 * WS_FLOATS + 2 * XS_FLOATS + HS_FLOATS) * 4)  // 95744

__device__ __forceinline__ void gemm_prefetch(float* ws, float* xs,
                                              const float* __restrict__ x,
                                              const float* __restrict__ W,
                                              int i, int cpair, int tid) {
    const float4* wsrc = (const float4*)(W + ((size_t)i * NC + cpair * 2) * (PP * QQ));
#pragma unroll
    for (int k = 0; k < 16; k++) {
        int j4 = tid + 128 * k;          // [0,2048)
        int cl = j4 >> 10;
        int p = (j4 >> 4) & 63;
        int q4 = j4 & 15;
        cp16(ws + p * WS_STRIDE + cl * QQ + q4 * 4, wsrc + j4);
    }
#pragma unroll
    for (int k = 0; k < 4; k++) {
        int j = tid + 128 * k;           // [0,512)
        int b = j >> 4;
        int p4 = j & 15;
        cp16(xs + b * XS_STRIDE + p4 * 4, x + ((size_t)b * IC + i) * PP + p4 * 4);
    }
}

__global__ __launch_bounds__(128, 2) void gemm_kernel(const float* __restrict__ x,
                                                      const float* __restrict__ W,
                                                      const float* __restrict__ bias) {
    extern __shared__ __align__(16) float smem[];
    __shared__ float c0sh[ICH][2];
    float* ws0 = smem;
    float* ws1 = smem + WS_FLOATS;
    float* xs0 = smem + 2 * WS_FLOATS;
    float* xs1 = xs0 + XS_FLOATS;
    __half* stag = (__half*)(xs1 + XS_FLOATS);   // [32 rows][136 halfs]

    int tid = threadIdx.x;
    int warp = tid >> 5;
    int lane = tid & 31;
    int g = lane >> 2;      // 0..7
    int tig = lane & 3;     // 0..3
    int cpair = blockIdx.x;
    int iblk = blockIdx.y;
    int i0 = iblk * ICH;
    int n0 = warp * 32;               // slice within 128-wide N
    int cl = warp >> 1;               // capsule-local
    int c = cpair * 2 + cl;
    int qn = n0 & 63;
    int qbase = qn + tig * 2;

    gemm_prefetch(ws0, xs0, x, W, i0, cpair, tid);
    cp_commit();

    // fused c0 = softmax_c(bias) for this CTA's rows (overlaps first loads)
    if (tid < ICH) {
        const float* bp = bias + (size_t)(i0 + tid) * NC;
        float m = -1e30f;
#pragma unroll 8
        for (int cc = 0; cc < NC; cc++) m = fmaxf(m, bp[cc]);
        float s = 0.f;
#pragma unroll 8
        for (int cc = 0; cc < NC; cc++) s += __expf(bp[cc] - m);
        float inv = 1.f / s;
        c0sh[tid][0] = __expf(bp[cpair * 2 + 0] - m) * inv;
        c0sh[tid][1] = __expf(bp[cpair * 2 + 1] - m) * inv;
    }

    float s0[2][4][4];
#pragma unroll
    for (int mt = 0; mt < 2; mt++)
#pragma unroll
        for (int nt = 0; nt < 4; nt++)
#pragma unroll
            for (int j = 0; j < 4; j++) s0[mt][nt][j] = 0.f;

    for (int ii = 0; ii < ICH; ii++) {
        int i = i0 + ii;
        cp_wait<0>();
        __syncthreads();
        if (ii + 1 < ICH) {
            float* wsn = ((ii + 1) & 1) ? ws1 : ws0;
            float* xsn = ((ii + 1) & 1) ? xs1 : xs0;
            gemm_prefetch(wsn, xsn, x, W, i + 1, cpair, tid);
        }
        cp_commit();
        const float* wsc = (ii & 1) ? ws1 : ws0;
        const float* xsc = (ii & 1) ? xs1 : xs0;

        float d[2][4][4];
#pragma unroll
        for (int mt = 0; mt < 2; mt++)
#pragma unroll
            for (int nt = 0; nt < 4; nt++)
#pragma unroll
                for (int j = 0; j < 4; j++) d[mt][nt][j] = 0.f;

#pragma unroll
        for (int ks = 0; ks < 8; ks++) {
            float a[2][4];
#pragma unroll
            for (int mt = 0; mt < 2; mt++) {
                int base = (mt * 16 + g) * XS_STRIDE + ks * 8 + tig;
                a[mt][0] = xsc[base];
                a[mt][1] = xsc[base + 8 * XS_STRIDE];
                a[mt][2] = xsc[base + 4];
                a[mt][3] = xsc[base + 8 * XS_STRIDE + 4];
            }
#pragma unroll
            for (int nt = 0; nt < 4; nt++) {
                int bb = (ks * 8 + tig) * WS_STRIDE + n0 + nt * 8 + g;
                float b0 = wsc[bb];
                float b1 = wsc[bb + 4 * WS_STRIDE];
                MMA_TF32(d[0][nt], a[0], b0, b1);
                MMA_TF32(d[1][nt], a[1], b0, b1);
            }
        }

        // S0 fused accumulation + stage hat tile in smem (conflict-free STS)
        float wgt = c0sh[ii][cl];
#pragma unroll
        for (int mt = 0; mt < 2; mt++) {
#pragma unroll
            for (int nt = 0; nt < 4; nt++) {
                int row0 = mt * 16 + g;
                int ncol = n0 + nt * 8 + tig * 2;
                *(__half2*)(stag + row0 * HS_STRIDE + ncol) =
                    __floats2half2_rn(d[mt][nt][0], d[mt][nt][1]);
                *(__half2*)(stag + (row0 + 8) * HS_STRIDE + ncol) =
                    __floats2half2_rn(d[mt][nt][2], d[mt][nt][3]);
#pragma unroll
                for (int j = 0; j < 4; j++)
                    s0[mt][nt][j] = fmaf(wgt, d[mt][nt][j], s0[mt][nt][j]);
            }
        }
        __syncthreads();

        // coalesced writeback: staging row b (n 0..127) -> 256B contiguous gmem
        {
            int c16 = lane & 15;
            int rsub = lane >> 4;
#pragma unroll
            for (int k = 0; k < 4; k++) {
                int r = warp * 8 + k * 2 + rsub;
                uint4 v = *(const uint4*)(stag + r * HS_STRIDE + c16 * 8);
                __half* dst = g_hat + (((size_t)r * IC + i) * NC + cpair * 2) * QQ
                              + c16 * 8;
                *(uint4*)dst = v;
            }
        }
    }

    // non-atomic per-iblock S0 partials
    float* sp = g_S0p + (size_t)iblk * SV;
#pragma unroll
    for (int mt = 0; mt < 2; mt++) {
#pragma unroll
        for (int nt = 0; nt < 4; nt++) {
            int q = qbase + nt * 8;
            int b0r = mt * 16 + g;
            *(float2*)(sp + ((size_t)b0r * NC + c) * QQ + q) =
                make_float2(s0[mt][nt][0], s0[mt][nt][1]);
            *(float2*)(sp + ((size_t)(b0r + 8) * NC + c) * QQ + q) =
                make_float2(s0[mt][nt][2], s0[mt][nt][3]);
        }
    }
}

// ---------------- routing pass (rounds 1, 2) -------------------------------
// RICH=18 tiles/CTA in 6 groups of 3, 3-stage cp.async pipeline (wait<1>).
// Thread (c=tid>>3, jj=tid&7) owns hat [c*64+jj*8, +8) as packed half2 regs.
// Softmax computed redundantly in EVERY warp (no idle-warp window), weight via
// one in-warp shuffle. 2 barriers/group. 5 CTAs/SM.
#define RICH 18
#define IIB 3
#define NGRP (RICH / IIB)                          // 6
#define RT_GRP_HALFS (IIB * NC * QQ)               // 6144 halfs = 12 KB
#define RT_SMEM_BYTES (3 * RT_GRP_HALFS * 2 + IIB * NC * 4 + RICH * NC * 4)

__global__ __launch_bounds__(256, 5) void route_kernel(int round,
                                                       const float* __restrict__ bias) {
    extern __shared__ __align__(16) char rsm[];
    __half* hb = (__half*)rsm;                              // 3 x 12 KB
    float* tb = (float*)(rsm + 3 * RT_GRP_HALFS * 2);       // IIB*NC
    float* bsh = tb + IIB * NC;                             // RICH*NC

    const float* vin = (round == 1) ? g_v0 : g_v01;
    float* Sp = (round == 1) ? g_S1p : g_S2p;

    int tid = threadIdx.x;
    int lane = tid & 31;
    int b = blockIdx.y;
    int iblk = blockIdx.x;
    int i0 = iblk * RICH;
    int c = tid >> 3;       // owned capsule
    int jj = tid & 7;       // q-segment within capsule

    // loop-invariant v slice -> registers (8 floats)
    float vreg[8];
    *(float4*)&vreg[0] = *(const float4*)(vin + b * (NC * QQ) + tid * 8);
    *(float4*)&vreg[4] = *(const float4*)(vin + b * (NC * QQ) + tid * 8 + 4);

    // bias table preloaded off the critical path
    for (int j = tid; j < RICH * NC; j += 256) bsh[j] = bias[i0 * NC + j];

    const __half* hsrc = g_hat + (size_t)b * IC * (NC * QQ) + tid * 8;

    // prefetch groups 0 and 1 (separate commit groups)
#pragma unroll
    for (int t = 0; t < IIB; t++)
        cp16(hb + t * (NC * QQ) + tid * 8, hsrc + (size_t)(i0 + t) * (NC * QQ));
    cp_commit();
#pragma unroll
    for (int t = 0; t < IIB; t++)
        cp16(hb + RT_GRP_HALFS + t * (NC * QQ) + tid * 8,
             hsrc + (size_t)(i0 + IIB + t) * (NC * QQ));
    cp_commit();

    float racc[8];
#pragma unroll
    for (int j = 0; j < 8; j++) racc[j] = 0.f;

    for (int gg = 0; gg < NGRP; gg++) {
        cp_wait<1>();   // group gg ready; gg+1 may still be in flight
        __syncthreads();
        if (gg + 2 < NGRP) {
            __half* dst = hb + ((gg + 2) % 3) * RT_GRP_HALFS;
            int ib = i0 + (gg + 2) * IIB;
#pragma unroll
            for (int t = 0; t < IIB; t++)
                cp16(dst + t * (NC * QQ) + tid * 8,
                     hsrc + (size_t)(ib + t) * (NC * QQ));
        }
        cp_commit();    // empty group at tail keeps wait<1> semantics

        const __half* hbuf = hb + (gg % 3) * RT_GRP_HALFS;

        // phase 1: single LDS.128 per tile (packed half2 regs); logits
        uint4 hv[IIB];
#pragma unroll
        for (int t = 0; t < IIB; t++)
            hv[t] = *(const uint4*)(hbuf + t * (NC * QQ) + tid * 8);
#pragma unroll
        for (int t = 0; t < IIB; t++) {
            const __half2* hp = (const __half2*)&hv[t];
            float s = 0.f;
#pragma unroll
            for (int j = 0; j < 4; j++) {
                float2 f = __half22float2(hp[j]);
                s = fmaf(f.x, vreg[2 * j], s);
                s = fmaf(f.y, vreg[2 * j + 1], s);
            }
            s += __shfl_down_sync(0xffffffffu, s, 4);
            s += __shfl_down_sync(0xffffffffu, s, 2);
            s += __shfl_down_sync(0xffffffffu, s, 1);
            if (jj == 0) tb[t * NC + c] = s + bsh[(gg * IIB + t) * NC + c];
        }
        __syncthreads();

        // phase 2 (merged): every warp redundantly computes softmax per tile
        // (lane <-> capsule), grabs its capsule's weight via one shuffle,
        // and accumulates. All warps busy; no extra barrier.
#pragma unroll
        for (int t = 0; t < IIB; t++) {
            float t_ = tb[t * NC + lane];   // conflict-free row read
            float m = t_;
#pragma unroll
            for (int o = 16; o > 0; o >>= 1)
                m = fmaxf(m, __shfl_xor_sync(0xffffffffu, m, o));
            float e = __expf(t_ - m);
            float se = e;
#pragma unroll
            for (int o = 16; o > 0; o >>= 1)
                se += __shfl_xor_sync(0xffffffffu, se, o);
            float w = e / se;
            float wc = __shfl_sync(0xffffffffu, w, c & 31);
            const __half2* hp = (const __half2*)&hv[t];
#pragma unroll
            for (int j = 0; j < 4; j++) {
                float2 f = __half22float2(hp[j]);
                racc[2 * j] = fmaf(wc, f.x, racc[2 * j]);
                racc[2 * j + 1] = fmaf(wc, f.y, racc[2 * j + 1]);
            }
        }
    }

    // non-atomic per-iblock partials (coalesced float4 stores)
    float* sp = Sp + ((size_t)iblk * BB + b) * (NC * QQ) + tid * 8;
    *(float4*)sp = make_float4(racc[0], racc[1], racc[2], racc[3]);
    *(float4*)(sp + 4) = make_float4(racc[4], racc[5], racc[6], racc[7]);
}

// ---------------- fused parallel reduce + squash ----------------
// Grid 256 (4 vecs per block), 256 threads, float4 loads.
// Thread (sl=t>>6, f4=t&63) sums its slice of the 256-float span (4 vecs);
// smem tree over 4 slices; 2-warp-per-vec squash.
// mode 0: S0p(36) -> v0 ; mode 1: S1p(64) -> v01 ; mode 2: S2p(64) -> out
__global__ __launch_bounds__(256) void reduce_squash_kernel(int mode,
                                                            float* __restrict__ dout) {
    __shared__ float red[4][4 * QQ];
    __shared__ float sspart[8];
    int t = threadIdx.x;
    int vb = blockIdx.x * 4;       // vec base (4 vecs share one b)
    int b = vb >> 5;
    int f4 = t & 63;               // float4 index within 256-float span
    int sl = t >> 6;               // slice 0..3

    float4 a = make_float4(0.f, 0.f, 0.f, 0.f);
    if (mode == 0) {
        const float4* base = (const float4*)(g_S0p + (size_t)vb * QQ);
#pragma unroll
        for (int k = 0; k < 9; k++) {
            int ib = sl * 9 + k;
            float4 v = base[(size_t)ib * (SV / 4) + f4];
            a.x += v.x; a.y += v.y; a.z += v.z; a.w += v.w;
        }
    } else {
        const float* Sp = (mode == 1) ? g_S1p : g_S2p;
        const float4* base =
            (const float4*)(Sp + (size_t)b * (NC * QQ) + (vb & 31) * QQ);
#pragma unroll
        for (int k = 0; k < 16; k++) {
            int ib = sl * 16 + k;
            float4 v = base[(size_t)ib * (BB * NC * QQ / 4) + f4];
            a.x += v.x; a.y += v.y; a.z += v.z; a.w += v.w;
        }
    }
    *(float4*)&red[sl][f4 * 4] = a;
    __syncthreads();

    float val = red[0][t] + red[1][t] + red[2][t] + red[3][t];
    // squared-norm per vec: 64 floats = 2 warps
    float ss = val * val;
#pragma unroll
    for (int o = 16; o > 0; o >>= 1)
        ss += __shfl_xor_sync(0xffffffffu, ss, o);
    if ((t & 31) == 0) sspart[t >> 5] = ss;
    __syncthreads();

    int vl = t >> 6;               // vec-local 0..3
    float sstot = sspart[vl * 2] + sspart[vl * 2 + 1];
    float sc = (sstot > 0.f) ? (sstot / (1.f + sstot)) * rsqrtf(sstot) : 0.f;
    float o = sc * val;
    int vec = vb + vl;
    int q = t & 63;
    if (mode == 0) {
        g_v0[vec * QQ + q] = o;
    } else if (mode == 1) {
        g_v01[vec * QQ + q] = g_v0[vec * QQ + q] + o;
    } else {
        dout[vec * QQ + q] = o;
    }
}

// ---------------- launch ----------------
extern "C" void kernel_launch(void* const* d_in, const int* in_sizes, int n_in,
                              void* d_out, int out_size) {
    const float* x = (const float*)d_in[0];     // [32,1152,64]
    const float* W = (const float*)d_in[1];     // [1152,32,64,64]
    const float* bias = (const float*)d_in[2];  // [1,1152,32,1]
    float* out = (float*)d_out;                 // [32,32,64]

    static int smem_set = 0;
    if (!smem_set) {
        cudaFuncSetAttribute(gemm_kernel, cudaFuncAttributeMaxDynamicSharedMemorySize,
                             GEMM_SMEM_BYTES);
        cudaFuncSetAttribute(route_kernel, cudaFuncAttributeMaxDynamicSharedMemorySize,
                             RT_SMEM_BYTES);
        smem_set = 1;
    }

    gemm_kernel<<<dim3(NC / 2, NIBLK), 128, GEMM_SMEM_BYTES>>>(x, W, bias);
    reduce_squash_kernel<<<BB * NC / 4, 256>>>(0, out);
    route_kernel<<<dim3(NRBLK, BB), 256, RT_SMEM_BYTES>>>(1, bias);
    reduce_squash_kernel<<<BB * NC / 4, 256>>>(1, out);
    route_kernel<<<dim3(NRBLK, BB), 256, RT_SMEM_BYTES>>>(2, bias);
    reduce_squash_kernel<<<BB * NC / 4, 256>>>(2, out);
}

// round 16
// speedup vs baseline: 1.1091x; 1.1091x over previous
#include <cuda_runtime.h>
#include <cuda_fp16.h>

// CapsuleLayer dynamic routing, GB300 sm_103a.
// B=32, IN_CAPS=1152, P=64, NUM_CAPS=32, Q=64, NUM_ROUTING=3.
//
// hat[b,i,c,q] = sum_p x[b,i,p] * W[i,c,p,q]   (tf32 mma.sync, stored fp16)
// r0: c0 = softmax_c(bias) batch-independent -> S0 partials inside GEMM (fp32)
// r1: b1 = bias + <hat,v0>_q ; S1 = sum_i softmax_c(b1)*hat ; v1=squash(S1)
// r2: b2 = bias + <hat,v0+v1>_q ; S2 = ... ; out = squash(S2)
// All S sums via non-atomic per-block partials, reduced in parallel squash kernels.

#define BB 32
#define IC 1152
#define PP 64
#define NC 32
#define QQ 64
#define HAT_ELEMS (BB * IC * NC * QQ)
#define SV (BB * NC * QQ)
#define NIBLK 36     // gemm i-blocks
#define NRBLK 64     // route i-blocks (IC / RICH)

// ---------------- device scratch ----------------
__device__ __align__(16) __half g_hat[HAT_ELEMS];      // 151 MB
__device__ __align__(16) float g_S0p[NIBLK * SV];      // 9.4 MB partials
__device__ __align__(16) float g_S1p[NRBLK * SV];      // 16.8 MB partials
__device__ __align__(16) float g_S2p[NRBLK * SV];      // 16.8 MB partials
__device__ __align__(16) float g_v0[SV];
__device__ __align__(16) float g_v01[SV];

// ---------------- helpers ----------------
__device__ __forceinline__ unsigned int fu(float f) { return __float_as_uint(f); }

__device__ __forceinline__ void cp16(const void* smem_dst, const void* gmem_src) {
    unsigned int s = (unsigned int)__cvta_generic_to_shared(smem_dst);
    asm volatile("cp.async.cg.shared.global [%0], [%1], 16;" :: "r"(s), "l"(gmem_src));
}
__device__ __forceinline__ void cp_commit() {
    asm volatile("cp.async.commit_group;");
}
template <int N>
__device__ __forceinline__ void cp_wait() {
    asm volatile("cp.async.wait_group %0;" :: "n"(N));
}

// tf32 m16n8k8: D += A*B. A row-major [16x8], B col-major [8x8], fp32 accum.
#define MMA_TF32(D, A, B0, B1)                                            \
    asm volatile(                                                          \
        "mma.sync.aligned.m16n8k8.row.col.f32.tf32.tf32.f32 "              \
        "{%0,%1,%2,%3},{%4,%5,%6,%7},{%8,%9},{%0,%1,%2,%3};"               \
        : "+f"((D)[0]), "+f"((D)[1]), "+f"((D)[2]), "+f"((D)[3])           \
        : "r"(fu((A)[0])), "r"(fu((A)[1])), "r"(fu((A)[2])), "r"(fu((A)[3])), \
          "r"(fu(B0)), "r"(fu(B1)))

// ---------------- GEMM (tf32): hat (fp16, staged) + S0 partials + fused c0 --
// Grid (16 cpairs, 36 iblocks), 128 threads (4 warps), 2 CTAs/SM.
#define ICH 32
#define WS_STRIDE 136     // 136 % 32 == 8 -> bank = 8k+n : conflict-free B reads
#define XS_STRIDE 68      // 68 % 32 == 4  -> bank = 4b+p : conflict-free A reads
#define HS_STRIDE 136     // halfs per staging row
#define WS_FLOATS (PP * WS_STRIDE)   // 8704
#define XS_FLOATS (BB * XS_STRIDE)   // 2176
#define HS_FLOATS (BB * HS_STRIDE / 2)
#define GEMM_SMEM_BYTES ((2 * WS_FLOATS + 2 * XS_FLOATS + HS_FLOATS) * 4)  // 95744

__device__ __forceinline__ void gemm_prefetch(float* ws, float* xs,
                                              const float* __restrict__ x,
                                              const float* __restrict__ W,
                                              int i, int cpair, int tid) {
    const float4* wsrc = (const float4*)(W + ((size_t)i * NC + cpair * 2) * (PP * QQ));
#pragma unroll
    for (int k = 0; k < 16; k++) {
        int j4 = tid + 128 * k;          // [0,2048)
        int cl = j4 >> 10;
        int p = (j4 >> 4) & 63;
        int q4 = j4 & 15;
        cp16(ws + p * WS_STRIDE + cl * QQ + q4 * 4, wsrc + j4);
    }
#pragma unroll
    for (int k = 0; k < 4; k++) {
        int j = tid + 128 * k;           // [0,512)
        int b = j >> 4;
        int p4 = j & 15;
        cp16(xs + b * XS_STRIDE + p4 * 4, x + ((size_t)b * IC + i) * PP + p4 * 4);
    }
}

__global__ __launch_bounds__(128, 2) void gemm_kernel(const float* __restrict__ x,
                                                      const float* __restrict__ W,
                                                      const float* __restrict__ bias) {
    extern __shared__ __align__(16) float smem[];
    __shared__ float c0sh[ICH][2];
    float* ws0 = smem;
    float* ws1 = smem + WS_FLOATS;
    float* xs0 = smem + 2 * WS_FLOATS;
    float* xs1 = xs0 + XS_FLOATS;
    __half* stag = (__half*)(xs1 + XS_FLOATS);   // [32 rows][136 halfs]

    int tid = threadIdx.x;
    int warp = tid >> 5;
    int lane = tid & 31;
    int g = lane >> 2;      // 0..7
    int tig = lane & 3;     // 0..3
    int cpair = blockIdx.x;
    int iblk = blockIdx.y;
    int i0 = iblk * ICH;
    int n0 = warp * 32;               // slice within 128-wide N
    int cl = warp >> 1;               // capsule-local
    int c = cpair * 2 + cl;
    int qn = n0 & 63;
    int qbase = qn + tig * 2;

    gemm_prefetch(ws0, xs0, x, W, i0, cpair, tid);
    cp_commit();

    // fused c0 = softmax_c(bias) for this CTA's rows (overlaps first loads)
    if (tid < ICH) {
        const float* bp = bias + (size_t)(i0 + tid) * NC;
        float m = -1e30f;
#pragma unroll 8
        for (int cc = 0; cc < NC; cc++) m = fmaxf(m, bp[cc]);
        float s = 0.f;
#pragma unroll 8
        for (int cc = 0; cc < NC; cc++) s += __expf(bp[cc] - m);
        float inv = 1.f / s;
        c0sh[tid][0] = __expf(bp[cpair * 2 + 0] - m) * inv;
        c0sh[tid][1] = __expf(bp[cpair * 2 + 1] - m) * inv;
    }

    float s0[2][4][4];
#pragma unroll
    for (int mt = 0; mt < 2; mt++)
#pragma unroll
        for (int nt = 0; nt < 4; nt++)
#pragma unroll
            for (int j = 0; j < 4; j++) s0[mt][nt][j] = 0.f;

    for (int ii = 0; ii < ICH; ii++) {
        int i = i0 + ii;
        cp_wait<0>();
        __syncthreads();
        if (ii + 1 < ICH) {
            float* wsn = ((ii + 1) & 1) ? ws1 : ws0;
            float* xsn = ((ii + 1) & 1) ? xs1 : xs0;
            gemm_prefetch(wsn, xsn, x, W, i + 1, cpair, tid);
        }
        cp_commit();
        const float* wsc = (ii & 1) ? ws1 : ws0;
        const float* xsc = (ii & 1) ? xs1 : xs0;

        float d[2][4][4];
#pragma unroll
        for (int mt = 0; mt < 2; mt++)
#pragma unroll
            for (int nt = 0; nt < 4; nt++)
#pragma unroll
                for (int j = 0; j < 4; j++) d[mt][nt][j] = 0.f;

#pragma unroll
        for (int ks = 0; ks < 8; ks++) {
            float a[2][4];
#pragma unroll
            for (int mt = 0; mt < 2; mt++) {
                int base = (mt * 16 + g) * XS_STRIDE + ks * 8 + tig;
                a[mt][0] = xsc[base];
                a[mt][1] = xsc[base + 8 * XS_STRIDE];
                a[mt][2] = xsc[base + 4];
                a[mt][3] = xsc[base + 8 * XS_STRIDE + 4];
            }
#pragma unroll
            for (int nt = 0; nt < 4; nt++) {
                int bb = (ks * 8 + tig) * WS_STRIDE + n0 + nt * 8 + g;
                float b0 = wsc[bb];
                float b1 = wsc[bb + 4 * WS_STRIDE];
                MMA_TF32(d[0][nt], a[0], b0, b1);
                MMA_TF32(d[1][nt], a[1], b0, b1);
            }
        }

        // S0 fused accumulation + stage hat tile in smem (conflict-free STS)
        float wgt = c0sh[ii][cl];
#pragma unroll
        for (int mt = 0; mt < 2; mt++) {
#pragma unroll
            for (int nt = 0; nt < 4; nt++) {
                int row0 = mt * 16 + g;
                int ncol = n0 + nt * 8 + tig * 2;
                *(__half2*)(stag + row0 * HS_STRIDE + ncol) =
                    __floats2half2_rn(d[mt][nt][0], d[mt][nt][1]);
                *(__half2*)(stag + (row0 + 8) * HS_STRIDE + ncol) =
                    __floats2half2_rn(d[mt][nt][2], d[mt][nt][3]);
#pragma unroll
                for (int j = 0; j < 4; j++)
                    s0[mt][nt][j] = fmaf(wgt, d[mt][nt][j], s0[mt][nt][j]);
            }
        }
        __syncthreads();

        // coalesced writeback: staging row b (n 0..127) -> 256B contiguous gmem
        {
            int c16 = lane & 15;
            int rsub = lane >> 4;
#pragma unroll
            for (int k = 0; k < 4; k++) {
                int r = warp * 8 + k * 2 + rsub;
                uint4 v = *(const uint4*)(stag + r * HS_STRIDE + c16 * 8);
                __half* dst = g_hat + (((size_t)r * IC + i) * NC + cpair * 2) * QQ
                              + c16 * 8;
                *(uint4*)dst = v;
            }
        }
    }

    // non-atomic per-iblock S0 partials
    float* sp = g_S0p + (size_t)iblk * SV;
#pragma unroll
    for (int mt = 0; mt < 2; mt++) {
#pragma unroll
        for (int nt = 0; nt < 4; nt++) {
            int q = qbase + nt * 8;
            int b0r = mt * 16 + g;
            *(float2*)(sp + ((size_t)b0r * NC + c) * QQ + q) =
                make_float2(s0[mt][nt][0], s0[mt][nt][1]);
            *(float2*)(sp + ((size_t)(b0r + 8) * NC + c) * QQ + q) =
                make_float2(s0[mt][nt][2], s0[mt][nt][3]);
        }
    }
}

// ---------------- routing pass (rounds 1, 2) -------------------------------
// RICH=18 tiles/CTA in 6 groups of 3. Direct LDG.128 register pipeline
// (cur/nxt uint4 per tile; next group's loads issued before current compute).
// Thread (c=tid>>3, jj=tid&7) owns hat [c*64+jj*8, +8).
// 3-phase structure (R14): logits -> barrier -> 3-warp softmax -> barrier ->
// accumulate. No cp.async, no hat smem. 4 CTAs/SM (reg-limited).
#define RICH 18
#define IIB 3
#define NGRP (RICH / IIB)                          // 6

__global__ __launch_bounds__(256, 4) void route_kernel(int round,
                                                       const float* __restrict__ bias) {
    __shared__ float tb[IIB * NC];
    __shared__ float csh[IIB * NC];
    __shared__ float bsh[RICH * NC];

    const float* vin = (round == 1) ? g_v0 : g_v01;
    float* Sp = (round == 1) ? g_S1p : g_S2p;

    int tid = threadIdx.x;
    int lane = tid & 31;
    int warp = tid >> 5;
    int b = blockIdx.y;
    int iblk = blockIdx.x;
    int i0 = iblk * RICH;
    int c = tid >> 3;       // owned capsule
    int jj = tid & 7;       // q-segment within capsule

    // loop-invariant v slice -> registers (8 floats)
    float vreg[8];
    *(float4*)&vreg[0] = *(const float4*)(vin + b * (NC * QQ) + tid * 8);
    *(float4*)&vreg[4] = *(const float4*)(vin + b * (NC * QQ) + tid * 8 + 4);

    // bias table preloaded off the critical path
    for (int j = tid; j < RICH * NC; j += 256) bsh[j] = bias[i0 * NC + j];

    const __half* hsrc = g_hat + (size_t)b * IC * (NC * QQ) + tid * 8;

    // register pipeline: group 0 -> cur
    uint4 cur[IIB], nxt[IIB];
#pragma unroll
    for (int t = 0; t < IIB; t++)
        cur[t] = *(const uint4*)(hsrc + (size_t)(i0 + t) * (NC * QQ));

    float racc[8];
#pragma unroll
    for (int j = 0; j < 8; j++) racc[j] = 0.f;

    for (int gg = 0; gg < NGRP; gg++) {
        // issue next group's loads first; scoreboard hides them behind
        // this group's compute + barriers
        if (gg + 1 < NGRP) {
            int ib = i0 + (gg + 1) * IIB;
#pragma unroll
            for (int t = 0; t < IIB; t++)
                nxt[t] = *(const uint4*)(hsrc + (size_t)(ib + t) * (NC * QQ));
        }

        // phase 1: logits from cur (register half2), 8-thread reduce
#pragma unroll
        for (int t = 0; t < IIB; t++) {
            const __half2* hp = (const __half2*)&cur[t];
            float s = 0.f;
#pragma unroll
            for (int j = 0; j < 4; j++) {
                float2 f = __half22float2(hp[j]);
                s = fmaf(f.x, vreg[2 * j], s);
                s = fmaf(f.y, vreg[2 * j + 1], s);
            }
            s += __shfl_down_sync(0xffffffffu, s, 4);
            s += __shfl_down_sync(0xffffffffu, s, 2);
            s += __shfl_down_sync(0xffffffffu, s, 1);
            if (jj == 0) tb[t * NC + c] = s + bsh[(gg * IIB + t) * NC + c];
        }
        __syncthreads();

        // phase 2: warp w < IIB -> softmax of tile w (lane <-> capsule)
        if (warp < IIB) {
            float t_ = tb[warp * NC + lane];
            float m = t_;
#pragma unroll
            for (int o = 16; o > 0; o >>= 1)
                m = fmaxf(m, __shfl_xor_sync(0xffffffffu, m, o));
            float e = __expf(t_ - m);
            float se = e;
#pragma unroll
            for (int o = 16; o > 0; o >>= 1)
                se += __shfl_xor_sync(0xffffffffu, se, o);
            csh[warp * NC + lane] = e / se;
        }
        __syncthreads();

        // phase 3: weighted accumulation (csh read is an 8-thread broadcast)
#pragma unroll
        for (int t = 0; t < IIB; t++) {
            float wc = csh[t * NC + c];
            const __half2* hp = (const __half2*)&cur[t];
#pragma unroll
            for (int j = 0; j < 4; j++) {
                float2 f = __half22float2(hp[j]);
                racc[2 * j] = fmaf(wc, f.x, racc[2 * j]);
                racc[2 * j + 1] = fmaf(wc, f.y, racc[2 * j + 1]);
            }
        }

#pragma unroll
        for (int t = 0; t < IIB; t++) cur[t] = nxt[t];
    }

    // non-atomic per-iblock partials (coalesced float4 stores)
    float* sp = Sp + ((size_t)iblk * BB + b) * (NC * QQ) + tid * 8;
    *(float4*)sp = make_float4(racc[0], racc[1], racc[2], racc[3]);
    *(float4*)(sp + 4) = make_float4(racc[4], racc[5], racc[6], racc[7]);
}

// ---------------- fused parallel reduce + squash ----------------
// Grid 1024 (one block per vec = b*NC+c), 256 threads.
// Thread (sl=t>>6, q=t&63) sums its partial slice; smem tree; warp 0 squashes.
// mode 0: S0p(36) -> v0 ; mode 1: S1p(64) -> v01 ; mode 2: S2p(64) -> out
__global__ __launch_bounds__(256) void reduce_squash_kernel(int mode,
                                                            float* __restrict__ dout) {
    __shared__ float red[4][QQ];
    int vec = blockIdx.x;
    int t = threadIdx.x;
    int q = t & 63, sl = t >> 6;
    int b = vec >> 5;
    int cq = (vec & 31) * QQ;

    float acc = 0.f;
    if (mode == 0) {
#pragma unroll
        for (int k = 0; k < 9; k++) {
            int ib = sl * 9 + k;
            acc += g_S0p[(size_t)ib * SV + (size_t)vec * QQ + q];
        }
    } else {
        const float* Sp = (mode == 1) ? g_S1p : g_S2p;
#pragma unroll
        for (int k = 0; k < 16; k++) {
            int ib = sl * 16 + k;
            acc += Sp[((size_t)ib * BB + b) * (NC * QQ) + cq + q];
        }
    }
    red[sl][q] = acc;
    __syncthreads();

    if (t < 32) {
        float x0 = red[0][t] + red[1][t] + red[2][t] + red[3][t];
        float x1 = red[0][t + 32] + red[1][t + 32] + red[2][t + 32] + red[3][t + 32];
        float ss = x0 * x0 + x1 * x1;
#pragma unroll
        for (int o = 16; o > 0; o >>= 1)
            ss += __shfl_xor_sync(0xffffffffu, ss, o);
        float sc = (ss > 0.f) ? (ss / (1.f + ss)) * rsqrtf(ss) : 0.f;
        float o0 = sc * x0, o1 = sc * x1;
        if (mode == 0) {
            g_v0[vec * QQ + t] = o0;
            g_v0[vec * QQ + 32 + t] = o1;
        } else if (mode == 1) {
            g_v01[vec * QQ + t] = g_v0[vec * QQ + t] + o0;
            g_v01[vec * QQ + 32 + t] = g_v0[vec * QQ + 32 + t] + o1;
        } else {
            dout[vec * QQ + t] = o0;
            dout[vec * QQ + 32 + t] = o1;
        }
    }
}

// ---------------- launch ----------------
extern "C" void kernel_launch(void* const* d_in, const int* in_sizes, int n_in,
                              void* d_out, int out_size) {
    const float* x = (const float*)d_in[0];     // [32,1152,64]
    const float* W = (const float*)d_in[1];     // [1152,32,64,64]
    const float* bias = (const float*)d_in[2];  // [1,1152,32,1]
    float* out = (float*)d_out;                 // [32,32,64]

    static int smem_set = 0;
    if (!smem_set) {
        cudaFuncSetAttribute(gemm_kernel, cudaFuncAttributeMaxDynamicSharedMemorySize,
                             GEMM_SMEM_BYTES);
        smem_set = 1;
    }

    gemm_kernel<<<dim3(NC / 2, NIBLK), 128, GEMM_SMEM_BYTES>>>(x, W, bias);
    reduce_squash_kernel<<<BB * NC, 256>>>(0, out);
    route_kernel<<<dim3(NRBLK, BB), 256>>>(1, bias);
    reduce_squash_kernel<<<BB * NC, 256>>>(1, out);
    route_kernel<<<dim3(NRBLK, BB), 256>>>(2, bias);
    reduce_squash_kernel<<<BB * NC, 256>>>(2, out);
}

// round 17
// speedup vs baseline: 1.1493x; 1.0363x over previous
#include <cuda_runtime.h>
#include <cuda_fp16.h>

// CapsuleLayer dynamic routing, GB300 sm_103a.
// B=32, IN_CAPS=1152, P=64, NUM_CAPS=32, Q=64, NUM_ROUTING=3.
//
// hat[b,i,c,q] = sum_p x[b,i,p] * W[i,c,p,q]   (tf32 mma.sync, stored fp16)
// r0: c0 = softmax_c(bias) batch-independent -> S0 partials inside GEMM
// r1: b1 = bias + <hat,v0>_q ; S1 = sum_i softmax_c(b1)*hat ; v1=squash(S1)
// r2: b2 = bias + <hat,v0+v1>_q ; S2 = ... ; out = squash(S2)
// S sums via non-atomic per-block fp16 partials, reduced in parallel kernels.

#define BB 32
#define IC 1152
#define PP 64
#define NC 32
#define QQ 64
#define HAT_ELEMS (BB * IC * NC * QQ)
#define SV (BB * NC * QQ)
#define NIBLK 36     // gemm i-blocks
#define NRBLK 64     // route i-blocks (IC / RICH)

// ---------------- device scratch ----------------
__device__ __align__(16) __half g_hat[HAT_ELEMS];      // 151 MB
__device__ __align__(16) __half g_S0p[NIBLK * SV];     // 4.7 MB fp16 partials
__device__ __align__(16) __half g_S1p[NRBLK * SV];     // 8.4 MB fp16 partials
__device__ __align__(16) __half g_S2p[NRBLK * SV];     // 8.4 MB fp16 partials
__device__ __align__(16) float g_v0[SV];
__device__ __align__(16) float g_v01[SV];

// ---------------- helpers ----------------
__device__ __forceinline__ unsigned int fu(float f) { return __float_as_uint(f); }
__device__ __forceinline__ unsigned int h2_as_u32(__half2 h) {
    union { __half2 h; unsigned int u; } cvt;
    cvt.h = h;
    return cvt.u;
}

__device__ __forceinline__ void cp16(const void* smem_dst, const void* gmem_src) {
    unsigned int s = (unsigned int)__cvta_generic_to_shared(smem_dst);
    asm volatile("cp.async.cg.shared.global [%0], [%1], 16;" :: "r"(s), "l"(gmem_src));
}
__device__ __forceinline__ void cp_commit() {
    asm volatile("cp.async.commit_group;");
}
template <int N>
__device__ __forceinline__ void cp_wait() {
    asm volatile("cp.async.wait_group %0;" :: "n"(N));
}

// tf32 m16n8k8: D += A*B. A row-major [16x8], B col-major [8x8], fp32 accum.
#define MMA_TF32(D, A, B0, B1)                                            \
    asm volatile(                                                          \
        "mma.sync.aligned.m16n8k8.row.col.f32.tf32.tf32.f32 "              \
        "{%0,%1,%2,%3},{%4,%5,%6,%7},{%8,%9},{%0,%1,%2,%3};"               \
        : "+f"((D)[0]), "+f"((D)[1]), "+f"((D)[2]), "+f"((D)[3])           \
        : "r"(fu((A)[0])), "r"(fu((A)[1])), "r"(fu((A)[2])), "r"(fu((A)[3])), \
          "r"(fu(B0)), "r"(fu(B1)))

// ---------------- GEMM (tf32): hat (fp16, staged) + S0 partials + fused c0 --
// Grid (16 cpairs, 36 iblocks), 128 threads (4 warps), 2 CTAs/SM.
#define ICH 32
#define WS_STRIDE 136     // 136 % 32 == 8 -> bank = 8k+n : conflict-free B reads
#define XS_STRIDE 68      // 68 % 32 == 4  -> bank = 4b+p : conflict-free A reads
#define HS_STRIDE 136     // halfs per staging row
#define WS_FLOATS (PP * WS_STRIDE)   // 8704
#define XS_FLOATS (BB * XS_STRIDE)   // 2176
#define HS_FLOATS (BB * HS_STRIDE / 2)
#define GEMM_SMEM_BYTES ((2 * WS_FLOATS + 2 * XS_FLOATS + HS_FLOATS) * 4)  // 95744

__device__ __forceinline__ void gemm_prefetch(float* ws, float* xs,
                                              const float* __restrict__ x,
                                              const float* __restrict__ W,
                                              int i, int cpair, int tid) {
    const float4* wsrc = (const float4*)(W + ((size_t)i * NC + cpair * 2) * (PP * QQ));
#pragma unroll
    for (int k = 0; k < 16; k++) {
        int j4 = tid + 128 * k;          // [0,2048)
        int cl = j4 >> 10;
        int p = (j4 >> 4) & 63;
        int q4 = j4 & 15;
        cp16(ws + p * WS_STRIDE + cl * QQ + q4 * 4, wsrc + j4);
    }
#pragma unroll
    for (int k = 0; k < 4; k++) {
        int j = tid + 128 * k;           // [0,512)
        int b = j >> 4;
        int p4 = j & 15;
        cp16(xs + b * XS_STRIDE + p4 * 4, x + ((size_t)b * IC + i) * PP + p4 * 4);
    }
}

__global__ __launch_bounds__(128, 2) void gemm_kernel(const float* __restrict__ x,
                                                      const float* __restrict__ W,
                                                      const float* __restrict__ bias) {
    extern __shared__ __align__(16) float smem[];
    __shared__ float c0sh[ICH][2];
    float* ws0 = smem;
    float* ws1 = smem + WS_FLOATS;
    float* xs0 = smem + 2 * WS_FLOATS;
    float* xs1 = xs0 + XS_FLOATS;
    __half* stag = (__half*)(xs1 + XS_FLOATS);   // [32 rows][136 halfs]

    int tid = threadIdx.x;
    int warp = tid >> 5;
    int lane = tid & 31;
    int g = lane >> 2;      // 0..7
    int tig = lane & 3;     // 0..3
    int cpair = blockIdx.x;
    int iblk = blockIdx.y;
    int i0 = iblk * ICH;
    int n0 = warp * 32;               // slice within 128-wide N
    int cl = warp >> 1;               // capsule-local
    int c = cpair * 2 + cl;
    int qn = n0 & 63;
    int qbase = qn + tig * 2;

    gemm_prefetch(ws0, xs0, x, W, i0, cpair, tid);
    cp_commit();

    // fused c0 = softmax_c(bias) for this CTA's rows (overlaps first loads)
    if (tid < ICH) {
        const float* bp = bias + (size_t)(i0 + tid) * NC;
        float m = -1e30f;
#pragma unroll 8
        for (int cc = 0; cc < NC; cc++) m = fmaxf(m, bp[cc]);
        float s = 0.f;
#pragma unroll 8
        for (int cc = 0; cc < NC; cc++) s += __expf(bp[cc] - m);
        float inv = 1.f / s;
        c0sh[tid][0] = __expf(bp[cpair * 2 + 0] - m) * inv;
        c0sh[tid][1] = __expf(bp[cpair * 2 + 1] - m) * inv;
    }

    float s0[2][4][4];
#pragma unroll
    for (int mt = 0; mt < 2; mt++)
#pragma unroll
        for (int nt = 0; nt < 4; nt++)
#pragma unroll
            for (int j = 0; j < 4; j++) s0[mt][nt][j] = 0.f;

    for (int ii = 0; ii < ICH; ii++) {
        int i = i0 + ii;
        cp_wait<0>();
        __syncthreads();
        if (ii + 1 < ICH) {
            float* wsn = ((ii + 1) & 1) ? ws1 : ws0;
            float* xsn = ((ii + 1) & 1) ? xs1 : xs0;
            gemm_prefetch(wsn, xsn, x, W, i + 1, cpair, tid);
        }
        cp_commit();
        const float* wsc = (ii & 1) ? ws1 : ws0;
        const float* xsc = (ii & 1) ? xs1 : xs0;

        float d[2][4][4];
#pragma unroll
        for (int mt = 0; mt < 2; mt++)
#pragma unroll
            for (int nt = 0; nt < 4; nt++)
#pragma unroll
                for (int j = 0; j < 4; j++) d[mt][nt][j] = 0.f;

#pragma unroll
        for (int ks = 0; ks < 8; ks++) {
            float a[2][4];
#pragma unroll
            for (int mt = 0; mt < 2; mt++) {
                int base = (mt * 16 + g) * XS_STRIDE + ks * 8 + tig;
                a[mt][0] = xsc[base];
                a[mt][1] = xsc[base + 8 * XS_STRIDE];
                a[mt][2] = xsc[base + 4];
                a[mt][3] = xsc[base + 8 * XS_STRIDE + 4];
            }
#pragma unroll
            for (int nt = 0; nt < 4; nt++) {
                int bb = (ks * 8 + tig) * WS_STRIDE + n0 + nt * 8 + g;
                float b0 = wsc[bb];
                float b1 = wsc[bb + 4 * WS_STRIDE];
                MMA_TF32(d[0][nt], a[0], b0, b1);
                MMA_TF32(d[1][nt], a[1], b0, b1);
            }
        }

        // S0 fused accumulation + stage hat tile in smem (conflict-free STS)
        float wgt = c0sh[ii][cl];
#pragma unroll
        for (int mt = 0; mt < 2; mt++) {
#pragma unroll
            for (int nt = 0; nt < 4; nt++) {
                int row0 = mt * 16 + g;
                int ncol = n0 + nt * 8 + tig * 2;
                *(__half2*)(stag + row0 * HS_STRIDE + ncol) =
                    __floats2half2_rn(d[mt][nt][0], d[mt][nt][1]);
                *(__half2*)(stag + (row0 + 8) * HS_STRIDE + ncol) =
                    __floats2half2_rn(d[mt][nt][2], d[mt][nt][3]);
#pragma unroll
                for (int j = 0; j < 4; j++)
                    s0[mt][nt][j] = fmaf(wgt, d[mt][nt][j], s0[mt][nt][j]);
            }
        }
        __syncthreads();

        // coalesced writeback: staging row b (n 0..127) -> 256B contiguous gmem
        {
            int c16 = lane & 15;
            int rsub = lane >> 4;
#pragma unroll
            for (int k = 0; k < 4; k++) {
                int r = warp * 8 + k * 2 + rsub;
                uint4 v = *(const uint4*)(stag + r * HS_STRIDE + c16 * 8);
                __half* dst = g_hat + (((size_t)r * IC + i) * NC + cpair * 2) * QQ
                              + c16 * 8;
                *(uint4*)dst = v;
            }
        }
    }

    // non-atomic per-iblock S0 partials (fp16)
    __half* sp = g_S0p + (size_t)iblk * SV;
#pragma unroll
    for (int mt = 0; mt < 2; mt++) {
#pragma unroll
        for (int nt = 0; nt < 4; nt++) {
            int q = qbase + nt * 8;
            int b0r = mt * 16 + g;
            *(__half2*)(sp + ((size_t)b0r * NC + c) * QQ + q) =
                __floats2half2_rn(s0[mt][nt][0], s0[mt][nt][1]);
            *(__half2*)(sp + ((size_t)(b0r + 8) * NC + c) * QQ + q) =
                __floats2half2_rn(s0[mt][nt][2], s0[mt][nt][3]);
        }
    }
}

// ---------------- routing pass (rounds 1, 2) -------------------------------
// RICH=18 tiles/CTA in 6 groups of 3. Direct LDG.128 register pipeline
// (cur/nxt uint4 per tile; next group's loads issued before current compute).
// Thread (c=tid>>3, jj=tid&7) owns hat [c*64+jj*8, +8).
// 3 phases: logits -> barrier -> 3-warp softmax -> barrier -> accumulate.
// fp16 per-iblock partials (one uint4 store/thread). 4 CTAs/SM.
#define RICH 18
#define IIB 3
#define NGRP (RICH / IIB)                          // 6

__global__ __launch_bounds__(256, 4) void route_kernel(int round,
                                                       const float* __restrict__ bias) {
    __shared__ float tb[IIB * NC];
    __shared__ float csh[IIB * NC];
    __shared__ float bsh[RICH * NC];

    const float* vin = (round == 1) ? g_v0 : g_v01;
    __half* Sp = (round == 1) ? g_S1p : g_S2p;

    int tid = threadIdx.x;
    int lane = tid & 31;
    int warp = tid >> 5;
    int b = blockIdx.y;
    int iblk = blockIdx.x;
    int i0 = iblk * RICH;
    int c = tid >> 3;       // owned capsule
    int jj = tid & 7;       // q-segment within capsule

    // loop-invariant v slice -> registers (8 floats)
    float vreg[8];
    *(float4*)&vreg[0] = *(const float4*)(vin + b * (NC * QQ) + tid * 8);
    *(float4*)&vreg[4] = *(const float4*)(vin + b * (NC * QQ) + tid * 8 + 4);

    // bias table preloaded off the critical path
    for (int j = tid; j < RICH * NC; j += 256) bsh[j] = bias[i0 * NC + j];

    const __half* hsrc = g_hat + (size_t)b * IC * (NC * QQ) + tid * 8;

    // register pipeline: group 0 -> cur
    uint4 cur[IIB], nxt[IIB];
#pragma unroll
    for (int t = 0; t < IIB; t++)
        cur[t] = *(const uint4*)(hsrc + (size_t)(i0 + t) * (NC * QQ));

    float racc[8];
#pragma unroll
    for (int j = 0; j < 8; j++) racc[j] = 0.f;

    for (int gg = 0; gg < NGRP; gg++) {
        // issue next group's loads first; scoreboard hides them behind
        // this group's compute + barriers
        if (gg + 1 < NGRP) {
            int ib = i0 + (gg + 1) * IIB;
#pragma unroll
            for (int t = 0; t < IIB; t++)
                nxt[t] = *(const uint4*)(hsrc + (size_t)(ib + t) * (NC * QQ));
        }

        // phase 1: logits from cur (register half2), 8-thread reduce
#pragma unroll
        for (int t = 0; t < IIB; t++) {
            const __half2* hp = (const __half2*)&cur[t];
            float s = 0.f;
#pragma unroll
            for (int j = 0; j < 4; j++) {
                float2 f = __half22float2(hp[j]);
                s = fmaf(f.x, vreg[2 * j], s);
                s = fmaf(f.y, vreg[2 * j + 1], s);
            }
            s += __shfl_down_sync(0xffffffffu, s, 4);
            s += __shfl_down_sync(0xffffffffu, s, 2);
            s += __shfl_down_sync(0xffffffffu, s, 1);
            if (jj == 0) tb[t * NC + c] = s + bsh[(gg * IIB + t) * NC + c];
        }
        __syncthreads();

        // phase 2: warp w < IIB -> softmax of tile w (lane <-> capsule)
        if (warp < IIB) {
            float t_ = tb[warp * NC + lane];
            float m = t_;
#pragma unroll
            for (int o = 16; o > 0; o >>= 1)
                m = fmaxf(m, __shfl_xor_sync(0xffffffffu, m, o));
            float e = __expf(t_ - m);
            float se = e;
#pragma unroll
            for (int o = 16; o > 0; o >>= 1)
                se += __shfl_xor_sync(0xffffffffu, se, o);
            csh[warp * NC + lane] = e / se;
        }
        __syncthreads();

        // phase 3: weighted accumulation (csh read is an 8-thread broadcast)
#pragma unroll
        for (int t = 0; t < IIB; t++) {
            float wc = csh[t * NC + c];
            const __half2* hp = (const __half2*)&cur[t];
#pragma unroll
            for (int j = 0; j < 4; j++) {
                float2 f = __half22float2(hp[j]);
                racc[2 * j] = fmaf(wc, f.x, racc[2 * j]);
                racc[2 * j + 1] = fmaf(wc, f.y, racc[2 * j + 1]);
            }
        }

#pragma unroll
        for (int t = 0; t < IIB; t++) cur[t] = nxt[t];
    }

    // non-atomic fp16 per-iblock partials (one coalesced uint4 store)
    __half* sp = Sp + ((size_t)iblk * BB + b) * (NC * QQ) + tid * 8;
    uint4 st;
    st.x = h2_as_u32(__floats2half2_rn(racc[0], racc[1]));
    st.y = h2_as_u32(__floats2half2_rn(racc[2], racc[3]));
    st.z = h2_as_u32(__floats2half2_rn(racc[4], racc[5]));
    st.w = h2_as_u32(__floats2half2_rn(racc[6], racc[7]));
    *(uint4*)sp = st;
}

// ---------------- fused parallel reduce + squash (fp16 partials) ----------
// Grid 1024 (one block per vec = b*NC+c), 128 threads.
// Thread (sl=t>>5, qh=t&31) sums half2 slices; smem tree; warp 0 squashes.
// mode 0: S0p(36) -> v0 ; mode 1: S1p(64) -> v01 ; mode 2: S2p(64) -> out
__global__ __launch_bounds__(128) void reduce_squash_kernel(int mode,
                                                            float* __restrict__ dout) {
    __shared__ float red[4][QQ];
    int vec = blockIdx.x;
    int t = threadIdx.x;
    int qh = t & 31, sl = t >> 5;   // half2 index, slice
    int b = vec >> 5;

    float2 acc = make_float2(0.f, 0.f);
    if (mode == 0) {
        const __half2* base = (const __half2*)g_S0p + (size_t)vec * 32;
#pragma unroll
        for (int k = 0; k < 9; k++) {
            int ib = sl * 9 + k;
            float2 v = __half22float2(base[(size_t)ib * (SV / 2) + qh]);
            acc.x += v.x;
            acc.y += v.y;
        }
    } else {
        const __half2* Sp = (const __half2*)((mode == 1) ? g_S1p : g_S2p);
        const __half2* base = Sp + (size_t)b * (NC * QQ / 2) + (vec & 31) * 32;
#pragma unroll
        for (int k = 0; k < 16; k++) {
            int ib = sl * 16 + k;
            float2 v = __half22float2(base[(size_t)ib * (BB * NC * QQ / 2) + qh]);
            acc.x += v.x;
            acc.y += v.y;
        }
    }
    *(float2*)&red[sl][qh * 2] = acc;
    __syncthreads();

    if (t < 32) {
        float x0 = red[0][t] + red[1][t] + red[2][t] + red[3][t];
        float x1 = red[0][t + 32] + red[1][t + 32] + red[2][t + 32] + red[3][t + 32];
        float ss = x0 * x0 + x1 * x1;
#pragma unroll
        for (int o = 16; o > 0; o >>= 1)
            ss += __shfl_xor_sync(0xffffffffu, ss, o);
        float sc = (ss > 0.f) ? (ss / (1.f + ss)) * rsqrtf(ss) : 0.f;
        float o0 = sc * x0, o1 = sc * x1;
        if (mode == 0) {
            g_v0[vec * QQ + t] = o0;
            g_v0[vec * QQ + 32 + t] = o1;
        } else if (mode == 1) {
            g_v01[vec * QQ + t] = g_v0[vec * QQ + t] + o0;
            g_v01[vec * QQ + 32 + t] = g_v0[vec * QQ + 32 + t] + o1;
        } else {
            dout[vec * QQ + t] = o0;
            dout[vec * QQ + 32 + t] = o1;
        }
    }
}

// ---------------- launch ----------------
extern "C" void kernel_launch(void* const* d_in, const int* in_sizes, int n_in,
                              void* d_out, int out_size) {
    const float* x = (const float*)d_in[0];     // [32,1152,64]
    const float* W = (const float*)d_in[1];     // [1152,32,64,64]
    const float* bias = (const float*)d_in[2];  // [1,1152,32,1]
    float* out = (float*)d_out;                 // [32,32,64]

    static int smem_set = 0;
    if (!smem_set) {
        cudaFuncSetAttribute(gemm_kernel, cudaFuncAttributeMaxDynamicSharedMemorySize,
                             GEMM_SMEM_BYTES);
        smem_set = 1;
    }

    gemm_kernel<<<dim3(NC / 2, NIBLK), 128, GEMM_SMEM_BYTES>>>(x, W, bias);
    reduce_squash_kernel<<<BB * NC, 128>>>(0, out);
    route_kernel<<<dim3(NRBLK, BB), 256>>>(1, bias);
    reduce_squash_kernel<<<BB * NC, 128>>>(1, out);
    route_kernel<<<dim3(NRBLK, BB), 256>>>(2, bias);
    reduce_squash_kernel<<<BB * NC, 128>>>(2, out);
}